// round 2
// baseline (speedup 1.0000x reference)
#include <cuda_runtime.h>
#include <math.h>

// ---------------- problem constants ----------------
#define BATCH   8192
#define TSTEPS  99
#define DIN     32
#define DH      100
#define DHP     112          // padded hidden
#define GRP     8            // threads per row
#define JT      14           // hidden cols per thread
#define RW      16
#define RU      25
#define RP      28           // padded rank (phase-1 accumulators)
#define U2ST    20           // per-slice stride (words) in U2/Wc smem, conflict-free
#define NCLS    6
#define ROWS_CTA 16
#define NTHREADS 128
#define NGRID   (BATCH / ROWS_CTA)        // 512
#define XW_THREADS 256
#define XW_GRID  ((BATCH * TSTEPS * GRP) / XW_THREADS)   // 25344

// ---------------- device-global prepped weights + scratch ----------------
__device__ float g_Wcp[DIN * GRP * U2ST];    // [k][g][20] = W1@W2 sliced/padded
__device__ float g_U1p[DHP * RP];            // [slot = jl*8+g][28]
__device__ float g_U2p[RU * GRP * U2ST];     // [r][g][20]
__device__ float g_bb [DHP * 2];             // interleaved (bias_gate, bias_update)
__device__ float g_sc [2];                   // sigmoid(zeta), sigmoid(nu)
__device__ float g_xc [(size_t)BATCH * TSTEPS * GRP * 16];  // precomputed x@Wc, [rt][g][16]

// ---------------- packed f32x2 FMA + tanh.approx ----------------
__device__ __forceinline__ void fma2(float2& d, float2 a, float2 b) {
    asm("fma.rn.f32x2 %0, %1, %2, %0;"
        : "+l"(reinterpret_cast<unsigned long long&>(d))
        : "l"(reinterpret_cast<unsigned long long&>(a)),
          "l"(reinterpret_cast<unsigned long long&>(b)));
}
__device__ __forceinline__ float tanha(float x) {
    float r; asm("tanh.approx.f32 %0, %1;" : "=f"(r) : "f"(x)); return r;
}

// ---------------- setup: fold / pad / transpose weights ----------------
__global__ void setup_kernel(const float* __restrict__ W1, const float* __restrict__ W2,
                             const float* __restrict__ U1, const float* __restrict__ U2,
                             const float* __restrict__ bg, const float* __restrict__ bu,
                             const float* __restrict__ zeta, const float* __restrict__ nu) {
    int tid = threadIdx.x;
    // Wc = W1@W2 into [k][g][20]; cols 14..19 zero, j>=100 zero
    for (int idx = tid; idx < DIN * GRP * U2ST; idx += blockDim.x) {
        int k = idx / (GRP * U2ST);
        int rem = idx % (GRP * U2ST);
        int g = rem / U2ST, c = rem % U2ST;
        int j = g * JT + c;
        float s = 0.f;
        if (c < JT && j < DH)
            for (int r = 0; r < RW; r++) s = fmaf(W1[k * RW + r], W2[r * DH + j], s);
        g_Wcp[idx] = s;
    }
    // U1p: slot = jl*8+g maps to j = g*14+jl; rank padded to 28
    for (int idx = tid; idx < DHP * RP; idx += blockDim.x) {
        int slot = idx / RP, r = idx % RP;
        int jl = slot >> 3, g = slot & 7;
        int j = g * JT + jl;
        g_U1p[idx] = (j < DH && r < RU) ? U1[j * RU + r] : 0.f;
    }
    // U2p: [r][g][20]
    for (int idx = tid; idx < RU * GRP * U2ST; idx += blockDim.x) {
        int r = idx / (GRP * U2ST);
        int rem = idx % (GRP * U2ST);
        int g = rem / U2ST, c = rem % U2ST;
        int j = g * JT + c;
        g_U2p[idx] = (c < JT && j < DH) ? U2[r * DH + j] : 0.f;
    }
    for (int j = tid; j < DHP; j += blockDim.x) {
        g_bb[2 * j]     = (j < DH) ? bg[j] : 0.f;
        g_bb[2 * j + 1] = (j < DH) ? bu[j] : 0.f;
    }
    if (tid == 0) {
        g_sc[0] = 1.f / (1.f + expf(-zeta[0]));
        g_sc[1] = 1.f / (1.f + expf(-nu[0]));
    }
}

// ---------------- GEMM: xc[rt][g][0..15] = x[rt] @ Wc slice ----------------
__global__ void __launch_bounds__(XW_THREADS)
xw_kernel(const float* __restrict__ x) {
    __shared__ __align__(16) float Wcs[DIN * GRP * U2ST];   // 20 KB
    for (int i = threadIdx.x; i < DIN * GRP * U2ST; i += XW_THREADS) Wcs[i] = g_Wcp[i];
    __syncthreads();

    size_t gid = (size_t)blockIdx.x * XW_THREADS + threadIdx.x;
    size_t rt = gid >> 3;
    int g = (int)(gid & 7);
    const float4* xp = (const float4*)(x + rt * DIN);

    float2 acc[8];
#pragma unroll
    for (int i = 0; i < 8; i++) acc[i] = make_float2(0.f, 0.f);

#pragma unroll
    for (int k4 = 0; k4 < 8; k4++) {
        float4 xv = xp[k4];
#pragma unroll
        for (int e = 0; e < 4; e++) {
            float xk = (e == 0) ? xv.x : (e == 1) ? xv.y : (e == 2) ? xv.z : xv.w;
            float2 x2 = make_float2(xk, xk);
            const float4* w = (const float4*)(Wcs + (k4 * 4 + e) * (GRP * U2ST) + g * U2ST);
#pragma unroll
            for (int q = 0; q < 4; q++) {
                float4 wv = w[q];
                fma2(acc[2 * q],     x2, make_float2(wv.x, wv.y));
                fma2(acc[2 * q + 1], x2, make_float2(wv.z, wv.w));
            }
        }
    }
    float4* dst = (float4*)(g_xc + gid * 16);
#pragma unroll
    for (int q = 0; q < 4; q++)
        dst[q] = make_float4(acc[2 * q].x, acc[2 * q].y, acc[2 * q + 1].x, acc[2 * q + 1].y);
}

// ---------------- fused recurrent kernel ----------------
__global__ void __launch_bounds__(NTHREADS, 4)
grnn_kernel(const float* __restrict__ FC, const float* __restrict__ FCb,
            float* __restrict__ out) {
    __shared__ __align__(16) float U1s[DHP * RP];          // 12.25 KB
    __shared__ __align__(16) float U2s[RU * GRP * U2ST];   // 15.6 KB
    __shared__ __align__(16) float bbs[DHP * 2];           // 0.9 KB

    const int tid = threadIdx.x;
    for (int i = tid; i < DHP * RP; i += NTHREADS) U1s[i] = g_U1p[i];
    for (int i = tid; i < RU * GRP * U2ST; i += NTHREADS) U2s[i] = g_U2p[i];
    for (int i = tid; i < DHP * 2; i += NTHREADS) bbs[i] = g_bb[i];
    __syncthreads();

    const float sz = g_sc[0];
    const float sn = g_sc[1];

    const int g    = tid & 7;
    const int rloc = tid >> 3;
    const int row  = blockIdx.x * ROWS_CTA + rloc;
    const float* bbp = bbs + (g * JT) * 2;

    // xc base (float4 units): slice for (row, t, g) at ((row*99+t)*8+g)*4
    const float4* xc4 = (const float4*)g_xc;
    size_t xbase = ((size_t)row * TSTEPS * GRP + g) * 4;   // t=0
    const size_t xstep = (size_t)GRP * 4;                  // advance one t

    float2 H[JT / 2];
#pragma unroll
    for (int i = 0; i < JT / 2; i++) H[i] = make_float2(0.f, 0.f);

    // c accumulator holds current step's xc slice (8 float2 = 16 floats, last 2 pad)
    float2 c[8];
    {
        const float4* p = xc4 + xbase;
#pragma unroll
        for (int q = 0; q < 4; q++) {
            float4 v = p[q];
            c[2 * q]     = make_float2(v.x, v.y);
            c[2 * q + 1] = make_float2(v.z, v.w);
        }
    }

    for (int t = 0; t < TSTEPS; t++) {
        // prefetch next step's xc
        const size_t xn = xbase + ((t + 1 < TSTEPS) ? xstep : 0);
        float4 n0 = xc4[xn], n1 = xc4[xn + 1], n2 = xc4[xn + 2], n3 = xc4[xn + 3];
        xbase += xstep;

        // ---- phase 1: partial Hp = H_loc @ U1 ----
        float2 php[RP / 2];
#pragma unroll
        for (int i = 0; i < RP / 2; i++) php[i] = make_float2(0.f, 0.f);
#pragma unroll
        for (int jl = 0; jl < JT; jl++) {
            float hv = (jl & 1) ? H[jl >> 1].y : H[jl >> 1].x;
            float2 h2 = make_float2(hv, hv);
            const float4* urow = (const float4*)(U1s + (jl * GRP + g) * RP);
#pragma unroll
            for (int q = 0; q < 7; q++) {
                float4 u = urow[q];
                fma2(php[2 * q],     h2, make_float2(u.x, u.y));
                fma2(php[2 * q + 1], h2, make_float2(u.z, u.w));
            }
        }
        // ---- butterfly all-reduce over the 8 lanes of this row ----
#pragma unroll
        for (int i = 0; i < RP / 2; i++) {
            float sx = php[i].x, sy = php[i].y;
            sx += __shfl_xor_sync(0xffffffffu, sx, 1);
            sy += __shfl_xor_sync(0xffffffffu, sy, 1);
            sx += __shfl_xor_sync(0xffffffffu, sx, 2);
            sy += __shfl_xor_sync(0xffffffffu, sy, 2);
            sx += __shfl_xor_sync(0xffffffffu, sx, 4);
            sy += __shfl_xor_sync(0xffffffffu, sy, 4);
            php[i] = make_float2(sx, sy);
        }

        // ---- phase 2: c += Hp @ U2 (slice) ----
#pragma unroll
        for (int r = 0; r < RU; r++) {
            float hp = (r & 1) ? php[r >> 1].y : php[r >> 1].x;
            float2 h2 = make_float2(hp, hp);
            const float4* urow = (const float4*)(U2s + r * (GRP * U2ST) + g * U2ST);
#pragma unroll
            for (int q = 0; q < 4; q++) {
                float4 u = urow[q];
                fma2(c[2 * q],     h2, make_float2(u.x, u.y));
                fma2(c[2 * q + 1], h2, make_float2(u.z, u.w));
            }
        }

        // ---- elementwise gate/update (sigmoid via tanh, tanh.approx MUFU) ----
#pragma unroll
        for (int i = 0; i < JT / 2; i++) {
#pragma unroll
            for (int e = 0; e < 2; e++) {
                float cc = e ? c[i].y : c[i].x;
                int jl = 2 * i + e;
                float2 bb = *(const float2*)(bbp + 2 * jl);
                float gg = fmaf(0.5f, tanha(0.5f * (cc + bb.x)), 0.5f);
                float hh = tanha(cc + bb.y);
                float hn = fmaf(gg, (e ? H[i].y : H[i].x) - sz, fmaf(sn, hh, sz));
                if (e) H[i].y = hn; else H[i].x = hn;
            }
        }

        // ---- roll in prefetched xc ----
        c[0] = make_float2(n0.x, n0.y); c[1] = make_float2(n0.z, n0.w);
        c[2] = make_float2(n1.x, n1.y); c[3] = make_float2(n1.z, n1.w);
        c[4] = make_float2(n2.x, n2.y); c[5] = make_float2(n2.z, n2.w);
        c[6] = make_float2(n3.x, n3.y); c[7] = make_float2(n3.z, n3.w);
    }

    // ---- epilogue: score = H @ FC + FCbias ----
    float s[NCLS];
#pragma unroll
    for (int cix = 0; cix < NCLS; cix++) s[cix] = 0.f;
#pragma unroll
    for (int jl = 0; jl < JT; jl++) {
        int jg = g * JT + jl;
        if (jg < DH) {
            float hv = (jl & 1) ? H[jl >> 1].y : H[jl >> 1].x;
#pragma unroll
            for (int cix = 0; cix < NCLS; cix++)
                s[cix] = fmaf(hv, __ldg(FC + jg * NCLS + cix), s[cix]);
        }
    }
#pragma unroll
    for (int cix = 0; cix < NCLS; cix++) {
        s[cix] += __shfl_xor_sync(0xffffffffu, s[cix], 1);
        s[cix] += __shfl_xor_sync(0xffffffffu, s[cix], 2);
        s[cix] += __shfl_xor_sync(0xffffffffu, s[cix], 4);
    }
    if (g == 0) {
#pragma unroll
        for (int cix = 0; cix < NCLS; cix++)
            out[row * NCLS + cix] = s[cix] + __ldg(FCb + cix);
    }
}

// ---------------- launch ----------------
extern "C" void kernel_launch(void* const* d_in, const int* in_sizes, int n_in,
                              void* d_out, int out_size) {
    const float* x    = (const float*)d_in[0];
    const float* W1   = (const float*)d_in[1];
    const float* W2   = (const float*)d_in[2];
    const float* U1   = (const float*)d_in[3];
    const float* U2   = (const float*)d_in[4];
    const float* bg   = (const float*)d_in[5];
    const float* bu   = (const float*)d_in[6];
    const float* zeta = (const float*)d_in[7];
    const float* nu   = (const float*)d_in[8];
    const float* FC   = (const float*)d_in[9];
    const float* FCb  = (const float*)d_in[10];
    float* out = (float*)d_out;

    setup_kernel<<<1, 256>>>(W1, W2, U1, U2, bg, bu, zeta, nu);
    xw_kernel<<<XW_GRID, XW_THREADS>>>(x);
    grnn_kernel<<<NGRID, NTHREADS>>>(FC, FCb, out);
}

// round 3
// speedup vs baseline: 2.4601x; 2.4601x over previous
#include <cuda_runtime.h>
#include <math.h>

// ---------------- problem constants ----------------
#define BATCH    8192
#define TSTEPS   99
#define DIN      32
#define DH       100
#define DHP      112         // padded hidden
#define GRP      8           // lane-slices per row
#define JT       14          // hidden cols per slice
#define RPT      2           // rows per thread
#define RW       16
#define RU       25
#define RP       28          // padded rank
#define SLST     20          // slice stride (words) in U2/Wc smem: conflict-free
#define XST      36          // x smem row stride (words)
#define NCLS     6
#define NTHREADS 128
#define ROWS_CTA 32          // 128 thr / 8 grp * 2 rows
#define NGRID    (BATCH / ROWS_CTA)   // 256

// smem layout (floats)
#define OFF_U1   0                         // 112*28       = 3136 f
#define OFF_U2   (OFF_U1 + DHP * RP)       // 25*160       = 4000 f
#define OFF_WC   (OFF_U2 + RU * GRP * SLST)// 32*160       = 5120 f
#define OFF_BB   (OFF_WC + DIN * GRP * SLST)// 224 f
#define OFF_XS   (OFF_BB + DHP * 2)        // 2*32*36      = 2304 f
#define SMEM_FLOATS (OFF_XS + 2 * ROWS_CTA * XST)
#define SMEM_BYTES  (SMEM_FLOATS * 4)      // 59136 B

// ---------------- device-global prepped weights ----------------
__device__ float g_Wcp[DIN * GRP * SLST];   // [k][g][20] = (W1@W2) sliced
__device__ float g_U1p[DHP * RP];           // [slot = jl*8+g][28]
__device__ float g_U2p[RU * GRP * SLST];    // [r][g][20]
__device__ float g_bb [DHP * 2];            // interleaved (bias_gate, bias_update)
__device__ float g_sc [2];                  // sigmoid(zeta), sigmoid(nu)

// ---------------- packed f32x2 FMA + tanh.approx ----------------
__device__ __forceinline__ void fma2(float2& d, float2 a, float2 b) {
    asm("fma.rn.f32x2 %0, %1, %2, %0;"
        : "+l"(reinterpret_cast<unsigned long long&>(d))
        : "l"(reinterpret_cast<unsigned long long&>(a)),
          "l"(reinterpret_cast<unsigned long long&>(b)));
}
__device__ __forceinline__ float tanha(float x) {
    float r; asm("tanh.approx.f32 %0, %1;" : "=f"(r) : "f"(x)); return r;
}
__device__ __forceinline__ float elem4(float4 v, int e) {
    return (e == 0) ? v.x : (e == 1) ? v.y : (e == 2) ? v.z : v.w;
}

// ---------------- setup: fold / pad / transpose weights ----------------
__global__ void setup_kernel(const float* __restrict__ W1, const float* __restrict__ W2,
                             const float* __restrict__ U1, const float* __restrict__ U2,
                             const float* __restrict__ bg, const float* __restrict__ bu,
                             const float* __restrict__ zeta, const float* __restrict__ nu) {
    int tid = blockIdx.x * blockDim.x + threadIdx.x;
    int nth = gridDim.x * blockDim.x;
    for (int idx = tid; idx < DIN * GRP * SLST; idx += nth) {
        int k = idx / (GRP * SLST);
        int rem = idx % (GRP * SLST);
        int g = rem / SLST, c = rem % SLST;
        int j = g * JT + c;
        float s = 0.f;
        if (c < JT && j < DH)
            for (int r = 0; r < RW; r++) s = fmaf(W1[k * RW + r], W2[r * DH + j], s);
        g_Wcp[idx] = s;
    }
    for (int idx = tid; idx < DHP * RP; idx += nth) {
        int slot = idx / RP, r = idx % RP;
        int jl = slot >> 3, g = slot & 7;
        int j = g * JT + jl;
        g_U1p[idx] = (j < DH && r < RU) ? U1[j * RU + r] : 0.f;
    }
    for (int idx = tid; idx < RU * GRP * SLST; idx += nth) {
        int r = idx / (GRP * SLST);
        int rem = idx % (GRP * SLST);
        int g = rem / SLST, c = rem % SLST;
        int j = g * JT + c;
        g_U2p[idx] = (c < JT && j < DH) ? U2[r * DH + j] : 0.f;
    }
    for (int j = tid; j < DHP; j += nth) {
        g_bb[2 * j]     = (j < DH) ? bg[j] : 0.f;
        g_bb[2 * j + 1] = (j < DH) ? bu[j] : 0.f;
    }
    if (tid == 0) {
        g_sc[0] = 1.f / (1.f + expf(-zeta[0]));
        g_sc[1] = 1.f / (1.f + expf(-nu[0]));
    }
}

// ---------------- fused recurrent kernel ----------------
__global__ void __launch_bounds__(NTHREADS, 2)
grnn_kernel(const float* __restrict__ x, const float* __restrict__ FC,
            const float* __restrict__ FCb, float* __restrict__ out) {
    extern __shared__ __align__(16) float sm[];
    float* U1s = sm + OFF_U1;
    float* U2s = sm + OFF_U2;
    float* Wcs = sm + OFF_WC;
    float* bbs = sm + OFF_BB;
    float* xs  = sm + OFF_XS;   // [2][ROWS_CTA][XST]

    const int tid = threadIdx.x;
    for (int i = tid; i < DHP * RP; i += NTHREADS) U1s[i] = g_U1p[i];
    for (int i = tid; i < RU * GRP * SLST; i += NTHREADS) U2s[i] = g_U2p[i];
    for (int i = tid; i < DIN * GRP * SLST; i += NTHREADS) Wcs[i] = g_Wcp[i];
    for (int i = tid; i < DHP * 2; i += NTHREADS) bbs[i] = g_bb[i];

    const float sz = g_sc[0];
    const float sn = g_sc[1];

    const int g  = tid & 7;
    const int pr = tid >> 3;            // row-pair 0..15
    const int r0 = 2 * pr;              // local rows r0, r0+1
    const float* bbp = bbs + (g * JT) * 2;

    // x staging assignment: thread covers (srow, 8 floats)
    const int srow = tid >> 2;
    const int sf   = (tid & 3) * 8;
    const float* xg = x + (size_t)(blockIdx.x * ROWS_CTA + srow) * (TSTEPS * DIN) + sf;

    // prologue: stage t=0
    {
        float4 a = *(const float4*)(xg);
        float4 b = *(const float4*)(xg + 4);
        *(float4*)(xs + srow * XST + sf)     = a;
        *(float4*)(xs + srow * XST + sf + 4) = b;
    }
    __syncthreads();

    float2 H0[JT / 2], H1[JT / 2];
#pragma unroll
    for (int i = 0; i < JT / 2; i++) { H0[i] = make_float2(0.f, 0.f); H1[i] = make_float2(0.f, 0.f); }

    int p = 0;
    for (int t = 0; t < TSTEPS; t++) {
        // prefetch next step's x
        const int tn = (t + 1 < TSTEPS) ? (t + 1) : t;
        float4 na = *(const float4*)(xg + tn * DIN);
        float4 nb = *(const float4*)(xg + tn * DIN + 4);

        // ---- phase 1: partial Hp = H @ U1 (weights shared across both rows) ----
        float2 pa[RP / 2], pb[RP / 2];
#pragma unroll
        for (int i = 0; i < RP / 2; i++) { pa[i] = make_float2(0.f, 0.f); pb[i] = make_float2(0.f, 0.f); }
#pragma unroll
        for (int jl = 0; jl < JT; jl++) {
            float h0 = (jl & 1) ? H0[jl >> 1].y : H0[jl >> 1].x;
            float h1 = (jl & 1) ? H1[jl >> 1].y : H1[jl >> 1].x;
            float2 h0v = make_float2(h0, h0);
            float2 h1v = make_float2(h1, h1);
            const float4* urow = (const float4*)(U1s + (jl * GRP + g) * RP);
#pragma unroll
            for (int q = 0; q < 7; q++) {
                float4 u = urow[q];
                float2 ul = make_float2(u.x, u.y);
                float2 uh = make_float2(u.z, u.w);
                fma2(pa[2 * q],     h0v, ul);
                fma2(pa[2 * q + 1], h0v, uh);
                fma2(pb[2 * q],     h1v, ul);
                fma2(pb[2 * q + 1], h1v, uh);
            }
        }
        // ---- butterfly all-reduce over the 8 lanes of each row ----
#pragma unroll
        for (int i = 0; i < RP / 2; i++) {
            float ax = pa[i].x, ay = pa[i].y, bx = pb[i].x, by = pb[i].y;
            ax += __shfl_xor_sync(0xffffffffu, ax, 1);
            ay += __shfl_xor_sync(0xffffffffu, ay, 1);
            bx += __shfl_xor_sync(0xffffffffu, bx, 1);
            by += __shfl_xor_sync(0xffffffffu, by, 1);
            ax += __shfl_xor_sync(0xffffffffu, ax, 2);
            ay += __shfl_xor_sync(0xffffffffu, ay, 2);
            bx += __shfl_xor_sync(0xffffffffu, bx, 2);
            by += __shfl_xor_sync(0xffffffffu, by, 2);
            ax += __shfl_xor_sync(0xffffffffu, ax, 4);
            ay += __shfl_xor_sync(0xffffffffu, ay, 4);
            bx += __shfl_xor_sync(0xffffffffu, bx, 4);
            by += __shfl_xor_sync(0xffffffffu, by, 4);
            pa[i] = make_float2(ax, ay);
            pb[i] = make_float2(bx, by);
        }

        // ---- phase 2: c = x@Wc + Hp@U2 on this thread's slice, both rows ----
        float2 c0[8], c1[8];
#pragma unroll
        for (int i = 0; i < 8; i++) { c0[i] = make_float2(0.f, 0.f); c1[i] = make_float2(0.f, 0.f); }

        const float* xr0 = xs + p * (ROWS_CTA * XST) + r0 * XST;
        const float* xr1 = xr0 + XST;
#pragma unroll
        for (int k4 = 0; k4 < 8; k4++) {
            float4 xa = *(const float4*)(xr0 + k4 * 4);
            float4 xb = *(const float4*)(xr1 + k4 * 4);
#pragma unroll
            for (int e = 0; e < 4; e++) {
                float2 x0v = make_float2(elem4(xa, e), elem4(xa, e));
                float2 x1v = make_float2(elem4(xb, e), elem4(xb, e));
                const float4* w = (const float4*)(Wcs + (k4 * 4 + e) * (GRP * SLST) + g * SLST);
#pragma unroll
                for (int q = 0; q < 4; q++) {
                    float4 wv = w[q];
                    float2 wl = make_float2(wv.x, wv.y);
                    float2 wh = make_float2(wv.z, wv.w);
                    fma2(c0[2 * q],     x0v, wl);
                    fma2(c0[2 * q + 1], x0v, wh);
                    fma2(c1[2 * q],     x1v, wl);
                    fma2(c1[2 * q + 1], x1v, wh);
                }
            }
        }
#pragma unroll
        for (int r = 0; r < RU; r++) {
            float ha = (r & 1) ? pa[r >> 1].y : pa[r >> 1].x;
            float hb = (r & 1) ? pb[r >> 1].y : pb[r >> 1].x;
            float2 h0v = make_float2(ha, ha);
            float2 h1v = make_float2(hb, hb);
            const float4* u = (const float4*)(U2s + r * (GRP * SLST) + g * SLST);
#pragma unroll
            for (int q = 0; q < 4; q++) {
                float4 uv = u[q];
                float2 ul = make_float2(uv.x, uv.y);
                float2 uh = make_float2(uv.z, uv.w);
                fma2(c0[2 * q],     h0v, ul);
                fma2(c0[2 * q + 1], h0v, uh);
                fma2(c1[2 * q],     h1v, ul);
                fma2(c1[2 * q + 1], h1v, uh);
            }
        }

        // ---- elementwise gate/update (sigmoid = 0.5*tanh(z/2)+0.5) ----
#pragma unroll
        for (int i = 0; i < JT / 2; i++) {
#pragma unroll
            for (int e = 0; e < 2; e++) {
                int jl = 2 * i + e;
                float2 bb = *(const float2*)(bbp + 2 * jl);
                {
                    float cc = e ? c0[i].y : c0[i].x;
                    float gg = fmaf(0.5f, tanha(0.5f * (cc + bb.x)), 0.5f);
                    float hh = tanha(cc + bb.y);
                    float hn = fmaf(gg, (e ? H0[i].y : H0[i].x) - sz, fmaf(sn, hh, sz));
                    if (e) H0[i].y = hn; else H0[i].x = hn;
                }
                {
                    float cc = e ? c1[i].y : c1[i].x;
                    float gg = fmaf(0.5f, tanha(0.5f * (cc + bb.x)), 0.5f);
                    float hh = tanha(cc + bb.y);
                    float hn = fmaf(gg, (e ? H1[i].y : H1[i].x) - sz, fmaf(sn, hh, sz));
                    if (e) H1[i].y = hn; else H1[i].x = hn;
                }
            }
        }

        // ---- publish prefetched x into the other buffer ----
        {
            float* dst = xs + (p ^ 1) * (ROWS_CTA * XST) + srow * XST + sf;
            *(float4*)(dst)     = na;
            *(float4*)(dst + 4) = nb;
        }
        __syncthreads();
        p ^= 1;
    }

    // ---- epilogue: score = H @ FC + FCbias ----
    float s0[NCLS], s1[NCLS];
#pragma unroll
    for (int cix = 0; cix < NCLS; cix++) { s0[cix] = 0.f; s1[cix] = 0.f; }
#pragma unroll
    for (int jl = 0; jl < JT; jl++) {
        int jg = g * JT + jl;
        if (jg < DH) {
            float h0 = (jl & 1) ? H0[jl >> 1].y : H0[jl >> 1].x;
            float h1 = (jl & 1) ? H1[jl >> 1].y : H1[jl >> 1].x;
#pragma unroll
            for (int cix = 0; cix < NCLS; cix++) {
                float fc = __ldg(FC + jg * NCLS + cix);
                s0[cix] = fmaf(h0, fc, s0[cix]);
                s1[cix] = fmaf(h1, fc, s1[cix]);
            }
        }
    }
#pragma unroll
    for (int cix = 0; cix < NCLS; cix++) {
        s0[cix] += __shfl_xor_sync(0xffffffffu, s0[cix], 1);
        s1[cix] += __shfl_xor_sync(0xffffffffu, s1[cix], 1);
        s0[cix] += __shfl_xor_sync(0xffffffffu, s0[cix], 2);
        s1[cix] += __shfl_xor_sync(0xffffffffu, s1[cix], 2);
        s0[cix] += __shfl_xor_sync(0xffffffffu, s0[cix], 4);
        s1[cix] += __shfl_xor_sync(0xffffffffu, s1[cix], 4);
    }
    if (g == 0) {
        int row = blockIdx.x * ROWS_CTA + r0;
#pragma unroll
        for (int cix = 0; cix < NCLS; cix++) {
            float fb = __ldg(FCb + cix);
            out[(size_t)row * NCLS + cix]       = s0[cix] + fb;
            out[(size_t)(row + 1) * NCLS + cix] = s1[cix] + fb;
        }
    }
}

// ---------------- launch ----------------
extern "C" void kernel_launch(void* const* d_in, const int* in_sizes, int n_in,
                              void* d_out, int out_size) {
    const float* x    = (const float*)d_in[0];
    const float* W1   = (const float*)d_in[1];
    const float* W2   = (const float*)d_in[2];
    const float* U1   = (const float*)d_in[3];
    const float* U2   = (const float*)d_in[4];
    const float* bg   = (const float*)d_in[5];
    const float* bu   = (const float*)d_in[6];
    const float* zeta = (const float*)d_in[7];
    const float* nu   = (const float*)d_in[8];
    const float* FC   = (const float*)d_in[9];
    const float* FCb  = (const float*)d_in[10];
    float* out = (float*)d_out;

    // sticky attribute; harmless if it errors during capture (set on first call)
    cudaFuncSetAttribute(grnn_kernel, cudaFuncAttributeMaxDynamicSharedMemorySize, SMEM_BYTES);

    setup_kernel<<<16, 256>>>(W1, W2, U1, U2, bg, bu, zeta, nu);
    grnn_kernel<<<NGRID, NTHREADS, SMEM_BYTES>>>(x, FC, FCb, out);
}